// round 2
// baseline (speedup 1.0000x reference)
#include <cuda_runtime.h>
#include <math.h>

// ClusteredAttention: b=4, l=4096, d=64 fp32.
// Row i (i < l-1) attends to {j < l-1 : label[j]==label[i]} ∪ {l-1}.
// Row l-1 attends to all keys. softmax(scale * scores), scale = 1/8.
//
// Dense masked flash-attention baseline:
//   grid = (L/BM, B), 256 threads, BM=BN=64, 4x4 register tiles,
//   online softmax, label mask -> -inf pre-softmax.
// Labels may arrive as int32 or int64 (JAX x64 off/on) -> runtime autodetect.

#define LSEQ 4096
#define HD   64
#define BM   64
#define BN   64
#define PAD  65
#define NTHREADS 256

__global__ __launch_bounds__(NTHREADS, 2)
void clustered_attn_kernel(const float* __restrict__ Q,
                           const float* __restrict__ K,
                           const float* __restrict__ V,
                           const int* __restrict__ lab32,
                           float* __restrict__ Out)
{
    extern __shared__ float sm[];
    float* Qt = sm;                  // [HD][PAD]  Qt[d*PAD + m]  (d-major, transposed)
    float* Kt = Qt + HD * PAD;       // [HD][PAD]  Kt[d*PAD + n]
    float* Pt = Kt + HD * PAD;       // [BN][PAD]  Pt[n*PAD + m]
    float* Vs = Pt + BN * PAD;       // [BN][HD]   Vs[n*HD + d]
    __shared__ int klabs[BN];
    __shared__ int lab_is64;

    const int b   = blockIdx.y;
    const int m0  = blockIdx.x * BM;
    const int tid = threadIdx.x;
    const int tx  = tid & 15;        // 0..15 -> key/out-dim tile
    const int ty  = tid >> 4;        // 0..15 -> query-row tile
    const int Lm1 = LSEQ - 1;
    const float scale = 0.125f;      // 1/sqrt(64)

    const float* Qb = Q + b * LSEQ * HD;
    const float* Kb = K + b * LSEQ * HD;
    const float* Vb = V + b * LSEQ * HD;
    const int labbase = b * Lm1;     // label index of this batch's row 0

    // ---- label dtype autodetect (values in [0,8): int64 => odd int32 words all 0).
    // Indices 1,3,...,63 are in-bounds under the int32 interpretation (the smaller one).
    if (tid == 0) {
        int f = 1;
        #pragma unroll
        for (int k = 0; k < 32; k++)
            if (lab32[2 * k + 1] != 0) { f = 0; break; }
        lab_is64 = f;
    }

    // ---- load Q tile transposed into shared (coalesced read, conflict-free write)
    #pragma unroll
    for (int idx = tid; idx < BM * HD; idx += NTHREADS) {
        int m = idx >> 6, d = idx & 63;
        Qt[d * PAD + m] = Qb[(m0 + m) * HD + d];
    }
    __syncthreads();   // lab_is64 + Qt visible

    const int is64 = lab_is64;

    // labels for my 4 query rows (-1 == time row, matches everything)
    int qlab[4];
    #pragma unroll
    for (int i = 0; i < 4; i++) {
        int gr = m0 + ty * 4 + i;
        int gi = labbase + gr;
        qlab[i] = (gr < Lm1) ? lab32[is64 ? (2 * gi) : gi] : -1;
    }

    float mrow[4], lrow[4], acc[4][4];
    #pragma unroll
    for (int i = 0; i < 4; i++) {
        mrow[i] = -INFINITY;
        lrow[i] = 0.0f;
        #pragma unroll
        for (int j = 0; j < 4; j++) acc[i][j] = 0.0f;
    }

    for (int n0 = 0; n0 < LSEQ; n0 += BN) {
        __syncthreads();  // previous iteration done reading Kt/Vs/Pt

        // ---- fill K (transposed) and V tiles + key labels
        #pragma unroll
        for (int idx = tid; idx < BN * HD; idx += NTHREADS) {
            int n = idx >> 6, d = idx & 63;
            Kt[d * PAD + n] = Kb[(n0 + n) * HD + d];
            Vs[n * HD + d]  = Vb[(n0 + n) * HD + d];
        }
        if (tid < BN) {
            int gn = n0 + tid;
            int gi = labbase + gn;
            klabs[tid] = (gn < Lm1) ? lab32[is64 ? (2 * gi) : gi] : -1;
        }
        __syncthreads();

        // ---- S = Q K^T : 4x4 tile per thread
        float s[4][4];
        #pragma unroll
        for (int i = 0; i < 4; i++)
            #pragma unroll
            for (int j = 0; j < 4; j++) s[i][j] = 0.0f;

        #pragma unroll 8
        for (int d = 0; d < HD; d++) {
            float a[4], bb[4];
            #pragma unroll
            for (int i = 0; i < 4; i++) a[i]  = Qt[d * PAD + 4 * ty + i];
            #pragma unroll
            for (int j = 0; j < 4; j++) bb[j] = Kt[d * PAD + 4 * tx + j];
            #pragma unroll
            for (int i = 0; i < 4; i++)
                #pragma unroll
                for (int j = 0; j < 4; j++) s[i][j] += a[i] * bb[j];
        }

        // ---- mask (cluster labels) + scale
        int klj[4];
        #pragma unroll
        for (int j = 0; j < 4; j++) klj[j] = klabs[4 * tx + j];

        #pragma unroll
        for (int i = 0; i < 4; i++) {
            #pragma unroll
            for (int j = 0; j < 4; j++) {
                bool ok = (qlab[i] < 0) || (klj[j] < 0) || (qlab[i] == klj[j]);
                s[i][j] = ok ? s[i][j] * scale : -INFINITY;
            }
        }

        // ---- online softmax (row stats reduced across the 16 threads sharing ty)
        #pragma unroll
        for (int i = 0; i < 4; i++) {
            float tm = s[i][0];
            tm = fmaxf(tm, s[i][1]);
            tm = fmaxf(tm, s[i][2]);
            tm = fmaxf(tm, s[i][3]);
            #pragma unroll
            for (int o = 8; o >= 1; o >>= 1)
                tm = fmaxf(tm, __shfl_xor_sync(0xffffffffu, tm, o));

            float newm = fmaxf(mrow[i], tm);
            // -inf-safe reference point: if nothing unmasked yet, exp args stay -inf -> 0
            float mref = (newm == -INFINITY) ? 0.0f : newm;
            float f = __expf(mrow[i] - mref);

            float rs = 0.0f;
            #pragma unroll
            for (int j = 0; j < 4; j++) {
                float p = __expf(s[i][j] - mref);
                s[i][j] = p;
                rs += p;
            }
            #pragma unroll
            for (int o = 8; o >= 1; o >>= 1)
                rs += __shfl_xor_sync(0xffffffffu, rs, o);

            lrow[i] = lrow[i] * f + rs;
            mrow[i] = newm;
            #pragma unroll
            for (int j = 0; j < 4; j++) acc[i][j] *= f;
        }

        // ---- stage P (transposed) for the O-GEMM
        #pragma unroll
        for (int i = 0; i < 4; i++)
            #pragma unroll
            for (int j = 0; j < 4; j++)
                Pt[(4 * tx + j) * PAD + (4 * ty + i)] = s[i][j];
        __syncthreads();

        // ---- O += P @ V : 4x4 tile per thread (rows m, cols d)
        #pragma unroll 8
        for (int n = 0; n < BN; n++) {
            float a[4], bb[4];
            #pragma unroll
            for (int i = 0; i < 4; i++) a[i]  = Pt[n * PAD + 4 * ty + i];
            #pragma unroll
            for (int j = 0; j < 4; j++) bb[j] = Vs[n * HD + 4 * tx + j];
            #pragma unroll
            for (int i = 0; i < 4; i++)
                #pragma unroll
                for (int j = 0; j < 4; j++) acc[i][j] += a[i] * bb[j];
        }
    }

    // ---- epilogue: normalize and store
    #pragma unroll
    for (int i = 0; i < 4; i++) {
        float inv = 1.0f / lrow[i];   // time-token column guarantees lrow > 0
        int gm = m0 + 4 * ty + i;
        float4 o4;
        o4.x = acc[i][0] * inv;
        o4.y = acc[i][1] * inv;
        o4.z = acc[i][2] * inv;
        o4.w = acc[i][3] * inv;
        *reinterpret_cast<float4*>(&Out[(b * LSEQ + gm) * HD + 4 * tx]) = o4;
    }
}

extern "C" void kernel_launch(void* const* d_in, const int* in_sizes, int n_in,
                              void* d_out, int out_size)
{
    const float* Q = (const float*)d_in[0];
    const float* K = (const float*)d_in[1];
    const float* V = (const float*)d_in[2];
    const int* lab = (const int*)d_in[3];   // int32 view; int64 handled in-kernel
    float* Out = (float*)d_out;

    const int B = in_sizes[0] / (LSEQ * HD);

    const int smem_bytes = (HD * PAD + HD * PAD + BN * PAD + BN * HD) * (int)sizeof(float);
    cudaFuncSetAttribute(clustered_attn_kernel,
                         cudaFuncAttributeMaxDynamicSharedMemorySize, smem_bytes);

    dim3 grid(LSEQ / BM, B);
    clustered_attn_kernel<<<grid, NTHREADS, smem_bytes>>>(Q, K, V, lab, Out);
}

// round 3
// speedup vs baseline: 2.8990x; 2.8990x over previous
#include <cuda_runtime.h>
#include <math.h>

// ClusteredAttention: b=4, l=4096, d=64 fp32, labels in [0,8).
// Block-sparse restructure: stable counting sort of tokens by label, gather
// Q/K/V into cluster-contiguous order, flash-attend each 64-query block only
// over its clusters' key segments (+ the global time key), scatter output.
// Time query (row l-1, attends all keys) handled by a dedicated small kernel.

#define LSEQ 4096
#define LM1  4095
#define HD   64
#define BM   64
#define BN   64
#define PAD  65
#define NTHREADS 256
#define MAXB 4

__device__ float g_Qs[MAXB * LSEQ * HD];
__device__ float g_Ks[MAXB * LSEQ * HD];
__device__ float g_Vs[MAXB * LSEQ * HD];
__device__ int   g_perm[MAXB * LSEQ];   // sorted pos -> original index
__device__ int   g_slab[MAXB * LSEQ];   // sorted labels; pos LM1 = -2 (time key sentinel)
__device__ int   g_segs[MAXB * 16];     // per batch: start[8], end[8]

// ---------------------------------------------------------------------------
// Kernel A: deterministic stable counting sort by label (one block per batch).
// Handles int32 or int64 label buffers via runtime autodetect.
// ---------------------------------------------------------------------------
__global__ void sort_kernel(const int* __restrict__ lab32)
{
    __shared__ int cnt[8][256];
    __shared__ int ex[8][256];
    __shared__ int tot[8];
    __shared__ int segstart[8];
    __shared__ int sh_is64;

    const int b = blockIdx.x;
    const int tid = threadIdx.x;

    if (tid == 0) {
        int f = 1;
        #pragma unroll
        for (int k = 0; k < 32; k++)
            if (lab32[2 * k + 1] != 0) { f = 0; break; }
        sh_is64 = f;
    }
    __syncthreads();
    const int is64 = sh_is64;
    const int labbase = b * LM1;

    // 16 consecutive tokens per thread; local histogram
    int mylab[16];
    int lh[8] = {0, 0, 0, 0, 0, 0, 0, 0};
    #pragma unroll
    for (int k = 0; k < 16; k++) {
        int i = tid * 16 + k;
        int l = -1;
        if (i < LM1) {
            int gi = labbase + i;
            l = lab32[is64 ? (2 * gi) : gi];
            lh[l]++;
        }
        mylab[k] = l;
    }
    #pragma unroll
    for (int l = 0; l < 8; l++) cnt[l][tid] = lh[l];
    __syncthreads();

    // warp w computes exclusive prefix over the 256 per-thread counts of label w
    {
        int w = tid >> 5, lane = tid & 31;
        int carry = 0;
        for (int c = 0; c < 8; c++) {
            int t = c * 32 + lane;
            int v = cnt[w][t];
            int x = v;
            #pragma unroll
            for (int o = 1; o < 32; o <<= 1) {
                int y = __shfl_up_sync(0xffffffffu, x, o);
                if (lane >= o) x += y;
            }
            ex[w][t] = carry + x - v;
            carry += __shfl_sync(0xffffffffu, x, 31);
        }
        if (lane == 0) tot[w] = carry;
    }
    __syncthreads();

    if (tid == 0) {
        int s = 0;
        #pragma unroll
        for (int l = 0; l < 8; l++) {
            segstart[l] = s;
            g_segs[b * 16 + l] = s;
            s += tot[l];
            g_segs[b * 16 + 8 + l] = s;
        }
        // time token at sorted pos LM1
        g_perm[b * LSEQ + LM1] = LM1;
        g_slab[b * LSEQ + LM1] = -2;   // never matched in tile loop
    }
    __syncthreads();

    int run[8] = {0, 0, 0, 0, 0, 0, 0, 0};
    #pragma unroll
    for (int k = 0; k < 16; k++) {
        int l = mylab[k];
        if (l >= 0) {
            int pos = segstart[l] + ex[l][tid] + run[l]++;
            int i = tid * 16 + k;
            g_perm[b * LSEQ + pos] = i;
            g_slab[b * LSEQ + pos] = l;
        }
    }
}

// ---------------------------------------------------------------------------
// Kernel B: gather Q/K/V rows into sorted order (float4 granularity).
// ---------------------------------------------------------------------------
__global__ void gather_kernel(const float* __restrict__ Q,
                              const float* __restrict__ K,
                              const float* __restrict__ V)
{
    int idx = blockIdx.x * blockDim.x + threadIdx.x;  // 0 .. B*LSEQ*16
    int r = idx >> 4;        // global sorted row (b*LSEQ + pos)
    int c = idx & 15;        // float4 slot within the 64-float row
    int b = r >> 12;
    int src = g_perm[r];
    long long so = ((long long)(b << 12) + src) * 16 + c;
    ((float4*)g_Qs)[r * 16 + c] = ((const float4*)Q)[so];
    ((float4*)g_Ks)[r * 16 + c] = ((const float4*)K)[so];
    ((float4*)g_Vs)[r * 16 + c] = ((const float4*)V)[so];
}

// ---------------------------------------------------------------------------
// Kernel C: main block-sparse flash attention over sorted tokens.
// ---------------------------------------------------------------------------
__global__ __launch_bounds__(NTHREADS, 2)
void clustered_attn_kernel(float* __restrict__ Out)
{
    extern __shared__ float sm[];
    float* Qt = sm;                  // [HD][PAD]  Qt[d*PAD + m] (d-major)
    float* Kt = Qt + HD * PAD;       // [HD][PAD]
    float* Pt = Kt + HD * PAD;       // [BN][PAD]
    float* Vs = Pt + BN * PAD;       // [BN][HD]
    __shared__ int klabs[BN];
    __shared__ float kt[HD];         // time key row
    __shared__ float vt[HD];         // time value row

    const int b   = blockIdx.y;
    const int m0  = blockIdx.x * BM;
    const int tid = threadIdx.x;
    const int tx  = tid & 15;
    const int ty  = tid >> 4;
    const float scale = 0.125f;

    const float* Qb = g_Qs + b * LSEQ * HD;
    const float* Kb = g_Ks + b * LSEQ * HD;
    const float* Vb = g_Vs + b * LSEQ * HD;
    const int* slab = g_slab + b * LSEQ;
    const int* segs = g_segs + b * 16;

    // ---- key tile range for this block (sorted clusters are contiguous)
    const int r_last = min(m0 + BM - 1, LM1 - 1);   // last real (non-time) row
    const int lab_f = slab[m0];
    const int lab_l = slab[r_last];
    const int kb = segs[lab_f] & ~(BN - 1);
    const int ke = min((segs[8 + lab_l] + BN - 1) & ~(BN - 1), LSEQ);

    // ---- load Q tile (transposed) + time K/V row
    #pragma unroll
    for (int idx = tid; idx < BM * HD; idx += NTHREADS) {
        int m = idx >> 6, d = idx & 63;
        Qt[d * PAD + m] = Qb[(m0 + m) * HD + d];
    }
    if (tid < HD) kt[tid] = Kb[LM1 * HD + tid];
    else if (tid < 2 * HD) vt[tid - HD] = Vb[LM1 * HD + (tid - HD)];

    // labels of my 4 query rows (-3 == inactive pad / time row, matches nothing)
    int qlab[4];
    #pragma unroll
    for (int i = 0; i < 4; i++) {
        int r = m0 + ty * 4 + i;
        qlab[i] = (r < LM1) ? slab[r] : -3;
    }

    float mrow[4], lrow[4], acc[4][4];
    #pragma unroll
    for (int i = 0; i < 4; i++) {
        mrow[i] = -INFINITY;
        lrow[i] = 0.0f;
        #pragma unroll
        for (int j = 0; j < 4; j++) acc[i][j] = 0.0f;
    }

    for (int n0 = kb; n0 < ke; n0 += BN) {
        __syncthreads();  // prev iter done reading tiles (and Qt/kt/vt stores on iter 0)

        #pragma unroll
        for (int idx = tid; idx < BN * HD; idx += NTHREADS) {
            int n = idx >> 6, d = idx & 63;
            Kt[d * PAD + n] = Kb[(n0 + n) * HD + d];
            Vs[n * HD + d]  = Vb[(n0 + n) * HD + d];
        }
        if (tid < BN) klabs[tid] = slab[n0 + tid];   // pos LM1 carries -2
        __syncthreads();

        // ---- S = Q K^T
        float s[4][4];
        #pragma unroll
        for (int i = 0; i < 4; i++)
            #pragma unroll
            for (int j = 0; j < 4; j++) s[i][j] = 0.0f;

        #pragma unroll 8
        for (int d = 0; d < HD; d++) {
            float a[4], bb[4];
            #pragma unroll
            for (int i = 0; i < 4; i++) a[i]  = Qt[d * PAD + 4 * ty + i];
            #pragma unroll
            for (int j = 0; j < 4; j++) bb[j] = Kt[d * PAD + 4 * tx + j];
            #pragma unroll
            for (int i = 0; i < 4; i++)
                #pragma unroll
                for (int j = 0; j < 4; j++) s[i][j] += a[i] * bb[j];
        }

        // ---- mask: only exact label match survives (sentinels never match)
        int klj[4];
        #pragma unroll
        for (int j = 0; j < 4; j++) klj[j] = klabs[4 * tx + j];

        #pragma unroll
        for (int i = 0; i < 4; i++)
            #pragma unroll
            for (int j = 0; j < 4; j++)
                s[i][j] = (qlab[i] == klj[j]) ? s[i][j] * scale : -INFINITY;

        // ---- online softmax (16-lane row groups)
        #pragma unroll
        for (int i = 0; i < 4; i++) {
            float tm = fmaxf(fmaxf(s[i][0], s[i][1]), fmaxf(s[i][2], s[i][3]));
            #pragma unroll
            for (int o = 8; o >= 1; o >>= 1)
                tm = fmaxf(tm, __shfl_xor_sync(0xffffffffu, tm, o));

            float newm = fmaxf(mrow[i], tm);
            float mref = (newm == -INFINITY) ? 0.0f : newm;
            float f = __expf(mrow[i] - mref);

            float rs = 0.0f;
            #pragma unroll
            for (int j = 0; j < 4; j++) {
                float p = __expf(s[i][j] - mref);
                s[i][j] = p;
                rs += p;
            }
            #pragma unroll
            for (int o = 8; o >= 1; o >>= 1)
                rs += __shfl_xor_sync(0xffffffffu, rs, o);

            lrow[i] = lrow[i] * f + rs;
            mrow[i] = newm;
            #pragma unroll
            for (int j = 0; j < 4; j++) acc[i][j] *= f;
        }

        // ---- stage P^T, then O += P @ V
        #pragma unroll
        for (int i = 0; i < 4; i++)
            #pragma unroll
            for (int j = 0; j < 4; j++)
                Pt[(4 * tx + j) * PAD + (4 * ty + i)] = s[i][j];
        __syncthreads();

        #pragma unroll 8
        for (int n = 0; n < BN; n++) {
            float a[4], bb[4];
            #pragma unroll
            for (int i = 0; i < 4; i++) a[i]  = Pt[n * PAD + 4 * ty + i];
            #pragma unroll
            for (int j = 0; j < 4; j++) bb[j] = Vs[n * HD + 4 * tx + j];
            #pragma unroll
            for (int i = 0; i < 4; i++)
                #pragma unroll
                for (int j = 0; j < 4; j++) acc[i][j] += a[i] * bb[j];
        }
    }

    // ---- time key: every real query attends to it (one scalar column)
    #pragma unroll
    for (int i = 0; i < 4; i++) {
        float part = 0.0f;
        #pragma unroll
        for (int jj = 0; jj < 4; jj++)
            part += Qt[(4 * tx + jj) * PAD + (4 * ty + i)] * kt[4 * tx + jj];
        #pragma unroll
        for (int o = 8; o >= 1; o >>= 1)
            part += __shfl_xor_sync(0xffffffffu, part, o);
        float st = part * scale;

        float newm = fmaxf(mrow[i], st);
        float f = __expf(mrow[i] - newm);
        float p = __expf(st - newm);
        lrow[i] = lrow[i] * f + p;
        mrow[i] = newm;
        #pragma unroll
        for (int j = 0; j < 4; j++)
            acc[i][j] = acc[i][j] * f + p * vt[4 * tx + j];
    }

    // ---- epilogue: normalize + scatter to original row
    #pragma unroll
    for (int i = 0; i < 4; i++) {
        int r = m0 + 4 * ty + i;
        if (r < LM1) {
            float inv = 1.0f / lrow[i];
            int orig = g_perm[b * LSEQ + r];
            float4 o4;
            o4.x = acc[i][0] * inv;
            o4.y = acc[i][1] * inv;
            o4.z = acc[i][2] * inv;
            o4.w = acc[i][3] * inv;
            *reinterpret_cast<float4*>(&Out[((long long)b * LSEQ + orig) * HD + 4 * tx]) = o4;
        }
    }
}

// ---------------------------------------------------------------------------
// Kernel D: the time query (row l-1) attends to ALL keys -> dense softmax.
// ---------------------------------------------------------------------------
__global__ void timeq_kernel(const float* __restrict__ Q,
                             const float* __restrict__ K,
                             const float* __restrict__ V,
                             float* __restrict__ Out)
{
    __shared__ float q[HD];
    __shared__ float sc[LSEQ];
    __shared__ float red[256];
    __shared__ float vacc[4][HD];

    const int b = blockIdx.x;
    const int tid = threadIdx.x;
    const float scale = 0.125f;

    if (tid < HD) q[tid] = Q[((long long)b * LSEQ + LM1) * HD + tid];
    __syncthreads();

    float m = -INFINITY;
    for (int j = tid; j < LSEQ; j += 256) {
        const float* kr = K + ((long long)b * LSEQ + j) * HD;
        float dot = 0.0f;
        #pragma unroll
        for (int d = 0; d < HD; d += 4) {
            float4 k4 = *reinterpret_cast<const float4*>(kr + d);
            dot += q[d] * k4.x + q[d + 1] * k4.y + q[d + 2] * k4.z + q[d + 3] * k4.w;
        }
        dot *= scale;
        sc[j] = dot;
        m = fmaxf(m, dot);
    }
    red[tid] = m; __syncthreads();
    for (int o = 128; o >= 1; o >>= 1) {
        if (tid < o) red[tid] = fmaxf(red[tid], red[tid + o]);
        __syncthreads();
    }
    m = red[0];
    __syncthreads();

    float s = 0.0f;
    for (int j = tid; j < LSEQ; j += 256) {
        float p = __expf(sc[j] - m);
        sc[j] = p;
        s += p;
    }
    red[tid] = s; __syncthreads();
    for (int o = 128; o >= 1; o >>= 1) {
        if (tid < o) red[tid] += red[tid + o];
        __syncthreads();
    }
    float inv = 1.0f / red[0];
    __syncthreads();

    const int d = tid & 63, ch = tid >> 6;
    float a = 0.0f;
    #pragma unroll 8
    for (int j = ch * 1024; j < (ch + 1) * 1024; j++)
        a += sc[j] * V[((long long)b * LSEQ + j) * HD + d];
    vacc[ch][d] = a;
    __syncthreads();

    if (tid < HD) {
        float o = (vacc[0][tid] + vacc[1][tid] + vacc[2][tid] + vacc[3][tid]) * inv;
        Out[((long long)b * LSEQ + LM1) * HD + tid] = o;
    }
}

// ---------------------------------------------------------------------------
extern "C" void kernel_launch(void* const* d_in, const int* in_sizes, int n_in,
                              void* d_out, int out_size)
{
    const float* Q = (const float*)d_in[0];
    const float* K = (const float*)d_in[1];
    const float* V = (const float*)d_in[2];
    const int* lab = (const int*)d_in[3];   // int32 view; int64 handled in sort
    float* Out = (float*)d_out;

    const int B = in_sizes[0] / (LSEQ * HD);

    sort_kernel<<<B, 256>>>(lab);
    gather_kernel<<<B * 256, 256>>>(Q, K, V);

    const int smem_bytes = (HD * PAD + HD * PAD + BN * PAD + BN * HD) * (int)sizeof(float);
    cudaFuncSetAttribute(clustered_attn_kernel,
                         cudaFuncAttributeMaxDynamicSharedMemorySize, smem_bytes);
    dim3 grid(LSEQ / BM, B);
    clustered_attn_kernel<<<grid, NTHREADS, smem_bytes>>>(Out);

    timeq_kernel<<<B, 256>>>(Q, K, V, Out);
}

// round 4
// speedup vs baseline: 3.8617x; 1.3321x over previous
#include <cuda_runtime.h>
#include <math.h>

// ClusteredAttention: b=4, l=4096, d=64 fp32, labels in [0,8).
// Block-sparse restructure: stable counting sort of tokens by label, gather
// Q/K/V into cluster-contiguous order, flash-attend each 64-query block only
// over its clusters' key segments (+ the global time key), scatter output.
// Time query (row l-1, attends all keys): split-softmax across 32 chunks
// (128 blocks) + tiny combine, replacing the 107us 4-block straggler.

#define LSEQ 4096
#define LM1  4095
#define HD   64
#define BM   64
#define BN   64
#define PAD  65
#define NTHREADS 256
#define MAXB 4
#define TQ_CHUNKS 128   // keys per timeq chunk
#define TQ_NCH    (LSEQ / TQ_CHUNKS)   // 32 chunks per batch

__device__ float g_Qs[MAXB * LSEQ * HD];
__device__ float g_Ks[MAXB * LSEQ * HD];
__device__ float g_Vs[MAXB * LSEQ * HD];
__device__ int   g_perm[MAXB * LSEQ];   // sorted pos -> original index
__device__ int   g_slab[MAXB * LSEQ];   // sorted labels; pos LM1 = -2 sentinel
__device__ int   g_segs[MAXB * 16];     // per batch: start[8], end[8]
__device__ float g_tq[MAXB * TQ_NCH * (HD + 2)];  // per-chunk: acc[64], m, s

// ---------------------------------------------------------------------------
// Kernel A: deterministic stable counting sort by label (one block per batch).
// ---------------------------------------------------------------------------
__global__ void sort_kernel(const int* __restrict__ lab32)
{
    __shared__ int cnt[8][256];
    __shared__ int ex[8][256];
    __shared__ int tot[8];
    __shared__ int segstart[8];
    __shared__ int sh_is64;

    const int b = blockIdx.x;
    const int tid = threadIdx.x;

    if (tid == 0) {
        int f = 1;
        #pragma unroll
        for (int k = 0; k < 32; k++)
            if (lab32[2 * k + 1] != 0) { f = 0; break; }
        sh_is64 = f;
    }
    __syncthreads();
    const int is64 = sh_is64;
    const int labbase = b * LM1;

    int mylab[16];
    int lh[8] = {0, 0, 0, 0, 0, 0, 0, 0};
    #pragma unroll
    for (int k = 0; k < 16; k++) {
        int i = tid * 16 + k;
        int l = -1;
        if (i < LM1) {
            int gi = labbase + i;
            l = lab32[is64 ? (2 * gi) : gi];
            lh[l]++;
        }
        mylab[k] = l;
    }
    #pragma unroll
    for (int l = 0; l < 8; l++) cnt[l][tid] = lh[l];
    __syncthreads();

    {
        int w = tid >> 5, lane = tid & 31;
        int carry = 0;
        for (int c = 0; c < 8; c++) {
            int t = c * 32 + lane;
            int v = cnt[w][t];
            int x = v;
            #pragma unroll
            for (int o = 1; o < 32; o <<= 1) {
                int y = __shfl_up_sync(0xffffffffu, x, o);
                if (lane >= o) x += y;
            }
            ex[w][t] = carry + x - v;
            carry += __shfl_sync(0xffffffffu, x, 31);
        }
        if (lane == 0) tot[w] = carry;
    }
    __syncthreads();

    if (tid == 0) {
        int s = 0;
        #pragma unroll
        for (int l = 0; l < 8; l++) {
            segstart[l] = s;
            g_segs[b * 16 + l] = s;
            s += tot[l];
            g_segs[b * 16 + 8 + l] = s;
        }
        g_perm[b * LSEQ + LM1] = LM1;
        g_slab[b * LSEQ + LM1] = -2;
    }
    __syncthreads();

    int run[8] = {0, 0, 0, 0, 0, 0, 0, 0};
    #pragma unroll
    for (int k = 0; k < 16; k++) {
        int l = mylab[k];
        if (l >= 0) {
            int pos = segstart[l] + ex[l][tid] + run[l]++;
            int i = tid * 16 + k;
            g_perm[b * LSEQ + pos] = i;
            g_slab[b * LSEQ + pos] = l;
        }
    }
}

// ---------------------------------------------------------------------------
// Kernel B: gather Q/K/V rows into sorted order (float4 granularity).
// ---------------------------------------------------------------------------
__global__ void gather_kernel(const float* __restrict__ Q,
                              const float* __restrict__ K,
                              const float* __restrict__ V)
{
    int idx = blockIdx.x * blockDim.x + threadIdx.x;
    int r = idx >> 4;
    int c = idx & 15;
    int b = r >> 12;
    int src = g_perm[r];
    long long so = ((long long)(b << 12) + src) * 16 + c;
    ((float4*)g_Qs)[r * 16 + c] = ((const float4*)Q)[so];
    ((float4*)g_Ks)[r * 16 + c] = ((const float4*)K)[so];
    ((float4*)g_Vs)[r * 16 + c] = ((const float4*)V)[so];
}

// ---------------------------------------------------------------------------
// Kernel C: main block-sparse flash attention over sorted tokens.
// ---------------------------------------------------------------------------
__global__ __launch_bounds__(NTHREADS, 2)
void clustered_attn_kernel(float* __restrict__ Out)
{
    extern __shared__ float sm[];
    float* Qt = sm;                  // [HD][PAD]
    float* Kt = Qt + HD * PAD;       // [HD][PAD]
    float* Pt = Kt + HD * PAD;       // [BN][PAD]
    float* Vs = Pt + BN * PAD;       // [BN][HD]
    __shared__ int klabs[BN];
    __shared__ float kt[HD];
    __shared__ float vt[HD];

    const int b   = blockIdx.y;
    const int m0  = blockIdx.x * BM;
    const int tid = threadIdx.x;
    const int tx  = tid & 15;
    const int ty  = tid >> 4;
    const float scale = 0.125f;

    const float* Qb = g_Qs + b * LSEQ * HD;
    const float* Kb = g_Ks + b * LSEQ * HD;
    const float* Vb = g_Vs + b * LSEQ * HD;
    const int* slab = g_slab + b * LSEQ;
    const int* segs = g_segs + b * 16;

    const int r_last = min(m0 + BM - 1, LM1 - 1);
    const int lab_f = slab[m0];
    const int lab_l = slab[r_last];
    const int kb = segs[lab_f] & ~(BN - 1);
    const int ke = min((segs[8 + lab_l] + BN - 1) & ~(BN - 1), LSEQ);

    #pragma unroll
    for (int idx = tid; idx < BM * HD; idx += NTHREADS) {
        int m = idx >> 6, d = idx & 63;
        Qt[d * PAD + m] = Qb[(m0 + m) * HD + d];
    }
    if (tid < HD) kt[tid] = Kb[LM1 * HD + tid];
    else if (tid < 2 * HD) vt[tid - HD] = Vb[LM1 * HD + (tid - HD)];

    int qlab[4];
    #pragma unroll
    for (int i = 0; i < 4; i++) {
        int r = m0 + ty * 4 + i;
        qlab[i] = (r < LM1) ? slab[r] : -3;
    }

    float mrow[4], lrow[4], acc[4][4];
    #pragma unroll
    for (int i = 0; i < 4; i++) {
        mrow[i] = -INFINITY;
        lrow[i] = 0.0f;
        #pragma unroll
        for (int j = 0; j < 4; j++) acc[i][j] = 0.0f;
    }

    for (int n0 = kb; n0 < ke; n0 += BN) {
        __syncthreads();

        #pragma unroll
        for (int idx = tid; idx < BN * HD; idx += NTHREADS) {
            int n = idx >> 6, d = idx & 63;
            Kt[d * PAD + n] = Kb[(n0 + n) * HD + d];
            Vs[n * HD + d]  = Vb[(n0 + n) * HD + d];
        }
        if (tid < BN) klabs[tid] = slab[n0 + tid];
        __syncthreads();

        float s[4][4];
        #pragma unroll
        for (int i = 0; i < 4; i++)
            #pragma unroll
            for (int j = 0; j < 4; j++) s[i][j] = 0.0f;

        #pragma unroll 8
        for (int d = 0; d < HD; d++) {
            float a[4], bb[4];
            #pragma unroll
            for (int i = 0; i < 4; i++) a[i]  = Qt[d * PAD + 4 * ty + i];
            #pragma unroll
            for (int j = 0; j < 4; j++) bb[j] = Kt[d * PAD + 4 * tx + j];
            #pragma unroll
            for (int i = 0; i < 4; i++)
                #pragma unroll
                for (int j = 0; j < 4; j++) s[i][j] += a[i] * bb[j];
        }

        int klj[4];
        #pragma unroll
        for (int j = 0; j < 4; j++) klj[j] = klabs[4 * tx + j];

        #pragma unroll
        for (int i = 0; i < 4; i++)
            #pragma unroll
            for (int j = 0; j < 4; j++)
                s[i][j] = (qlab[i] == klj[j]) ? s[i][j] * scale : -INFINITY;

        #pragma unroll
        for (int i = 0; i < 4; i++) {
            float tm = fmaxf(fmaxf(s[i][0], s[i][1]), fmaxf(s[i][2], s[i][3]));
            #pragma unroll
            for (int o = 8; o >= 1; o >>= 1)
                tm = fmaxf(tm, __shfl_xor_sync(0xffffffffu, tm, o));

            float newm = fmaxf(mrow[i], tm);
            float mref = (newm == -INFINITY) ? 0.0f : newm;
            float f = __expf(mrow[i] - mref);

            float rs = 0.0f;
            #pragma unroll
            for (int j = 0; j < 4; j++) {
                float p = __expf(s[i][j] - mref);
                s[i][j] = p;
                rs += p;
            }
            #pragma unroll
            for (int o = 8; o >= 1; o >>= 1)
                rs += __shfl_xor_sync(0xffffffffu, rs, o);

            lrow[i] = lrow[i] * f + rs;
            mrow[i] = newm;
            #pragma unroll
            for (int j = 0; j < 4; j++) acc[i][j] *= f;
        }

        #pragma unroll
        for (int i = 0; i < 4; i++)
            #pragma unroll
            for (int j = 0; j < 4; j++)
                Pt[(4 * tx + j) * PAD + (4 * ty + i)] = s[i][j];
        __syncthreads();

        #pragma unroll 8
        for (int n = 0; n < BN; n++) {
            float a[4], bb[4];
            #pragma unroll
            for (int i = 0; i < 4; i++) a[i]  = Pt[n * PAD + 4 * ty + i];
            #pragma unroll
            for (int j = 0; j < 4; j++) bb[j] = Vs[n * HD + 4 * tx + j];
            #pragma unroll
            for (int i = 0; i < 4; i++)
                #pragma unroll
                for (int j = 0; j < 4; j++) acc[i][j] += a[i] * bb[j];
        }
    }

    // ---- time key column
    #pragma unroll
    for (int i = 0; i < 4; i++) {
        float part = 0.0f;
        #pragma unroll
        for (int jj = 0; jj < 4; jj++)
            part += Qt[(4 * tx + jj) * PAD + (4 * ty + i)] * kt[4 * tx + jj];
        #pragma unroll
        for (int o = 8; o >= 1; o >>= 1)
            part += __shfl_xor_sync(0xffffffffu, part, o);
        float st = part * scale;

        float newm = fmaxf(mrow[i], st);
        float f = __expf(mrow[i] - newm);
        float p = __expf(st - newm);
        lrow[i] = lrow[i] * f + p;
        mrow[i] = newm;
        #pragma unroll
        for (int j = 0; j < 4; j++)
            acc[i][j] = acc[i][j] * f + p * vt[4 * tx + j];
    }

    // ---- epilogue: normalize + scatter
    #pragma unroll
    for (int i = 0; i < 4; i++) {
        int r = m0 + 4 * ty + i;
        if (r < LM1) {
            float inv = 1.0f / lrow[i];
            int orig = g_perm[b * LSEQ + r];
            float4 o4;
            o4.x = acc[i][0] * inv;
            o4.y = acc[i][1] * inv;
            o4.z = acc[i][2] * inv;
            o4.w = acc[i][3] * inv;
            *reinterpret_cast<float4*>(&Out[((long long)b * LSEQ + orig) * HD + 4 * tx]) = o4;
        }
    }
}

// ---------------------------------------------------------------------------
// Kernel D1: time-query partials. Grid = B*TQ_NCH blocks, 128 threads.
// Each block: 128 keys -> chunk max m_c, sum s_c, weighted-V partial acc[64].
// ---------------------------------------------------------------------------
__global__ void timeq_part(const float* __restrict__ Q,
                           const float* __restrict__ K,
                           const float* __restrict__ V)
{
    __shared__ float q[HD];
    __shared__ float p[TQ_CHUNKS];
    __shared__ float red[128];
    __shared__ float vacc[2][HD];

    const int b = blockIdx.x >> 5;      // TQ_NCH = 32
    const int c = blockIdx.x & 31;
    const int tid = threadIdx.x;
    const float scale = 0.125f;
    const long long base = (long long)b * LSEQ;

    if (tid < HD) q[tid] = Q[(base + LM1) * HD + tid];
    __syncthreads();

    // one key per thread
    const int j = c * TQ_CHUNKS + tid;
    const float* kr = K + (base + j) * HD;
    float dot = 0.0f;
    #pragma unroll
    for (int d = 0; d < HD; d += 4) {
        float4 k4 = *reinterpret_cast<const float4*>(kr + d);
        dot += q[d] * k4.x + q[d + 1] * k4.y + q[d + 2] * k4.z + q[d + 3] * k4.w;
    }
    dot *= scale;

    // block max
    float m = dot;
    #pragma unroll
    for (int o = 16; o >= 1; o >>= 1)
        m = fmaxf(m, __shfl_xor_sync(0xffffffffu, m, o));
    if ((tid & 31) == 0) red[tid >> 5] = m;
    __syncthreads();
    m = fmaxf(fmaxf(red[0], red[1]), fmaxf(red[2], red[3]));

    float pv = __expf(dot - m);
    p[tid] = pv;

    // block sum
    float s = pv;
    #pragma unroll
    for (int o = 16; o >= 1; o >>= 1)
        s += __shfl_xor_sync(0xffffffffu, s, o);
    if ((tid & 31) == 0) red[4 + (tid >> 5)] = s;
    __syncthreads();
    s = red[4] + red[5] + red[6] + red[7];

    // partial weighted V: thread (h,d) sums 64 keys
    const int d = tid & 63, h = tid >> 6;
    float a = 0.0f;
    #pragma unroll 8
    for (int jj = h * 64; jj < h * 64 + 64; jj++)
        a += p[jj] * V[(base + c * TQ_CHUNKS + jj) * HD + d];
    vacc[h][d] = a;
    __syncthreads();

    float* out = g_tq + (b * TQ_NCH + c) * (HD + 2);
    if (tid < HD) out[tid] = vacc[0][tid] + vacc[1][tid];
    else if (tid == HD) { out[HD] = m; out[HD + 1] = s; }
}

// ---------------------------------------------------------------------------
// Kernel D2: combine time-query partials. Grid = B, 64 threads.
// ---------------------------------------------------------------------------
__global__ void timeq_combine(float* __restrict__ Out)
{
    const int b = blockIdx.x;
    const int tid = threadIdx.x;   // = output dim d
    const float* part = g_tq + b * TQ_NCH * (HD + 2);

    float M = -INFINITY;
    #pragma unroll
    for (int c = 0; c < TQ_NCH; c++)
        M = fmaxf(M, part[c * (HD + 2) + HD]);

    float stot = 0.0f, a = 0.0f;
    #pragma unroll
    for (int c = 0; c < TQ_NCH; c++) {
        float f = __expf(part[c * (HD + 2) + HD] - M);
        stot += part[c * (HD + 2) + HD + 1] * f;
        a    += part[c * (HD + 2) + tid] * f;
    }
    Out[((long long)b * LSEQ + LM1) * HD + tid] = a / stot;
}

// ---------------------------------------------------------------------------
extern "C" void kernel_launch(void* const* d_in, const int* in_sizes, int n_in,
                              void* d_out, int out_size)
{
    const float* Q = (const float*)d_in[0];
    const float* K = (const float*)d_in[1];
    const float* V = (const float*)d_in[2];
    const int* lab = (const int*)d_in[3];
    float* Out = (float*)d_out;

    const int B = in_sizes[0] / (LSEQ * HD);

    sort_kernel<<<B, 256>>>(lab);
    gather_kernel<<<B * 256, 256>>>(Q, K, V);

    const int smem_bytes = (HD * PAD + HD * PAD + BN * PAD + BN * HD) * (int)sizeof(float);
    cudaFuncSetAttribute(clustered_attn_kernel,
                         cudaFuncAttributeMaxDynamicSharedMemorySize, smem_bytes);
    dim3 grid(LSEQ / BM, B);
    clustered_attn_kernel<<<grid, NTHREADS, smem_bytes>>>(Out);

    timeq_part<<<B * TQ_NCH, 128>>>(Q, K, V);
    timeq_combine<<<B, HD>>>(Out);
}

// round 5
// speedup vs baseline: 5.1694x; 1.3386x over previous
#include <cuda_runtime.h>
#include <math.h>

// ClusteredAttention: b=4, l=4096, d=64 fp32, labels in [0,8).
// Counting-sort tokens by label, gather Q/K/V cluster-contiguous, then
// CLUSTER-ALIGNED block scheduling: each 64-query block belongs to exactly
// one cluster and scans only that cluster's aligned key tiles (+ time key).
// Time query handled by split-softmax (part + combine).

#define LSEQ 4096
#define LM1  4095
#define HD   64
#define BM   64
#define BN   64
#define PAD  65
#define NTHREADS 256
#define MAXB 4
#define MAXBLK 72
#define TQ_CHUNKS 128
#define TQ_NCH    (LSEQ / TQ_CHUNKS)

__device__ float g_Qs[MAXB * LSEQ * HD];
__device__ float g_Ks[MAXB * LSEQ * HD];
__device__ float g_Vs[MAXB * LSEQ * HD];
__device__ int   g_perm[MAXB * LSEQ];   // sorted pos -> original index
__device__ int   g_slab[MAXB * LSEQ];   // sorted labels; pos LM1 = -2 sentinel
__device__ int4  g_btab[MAXB * MAXBLK]; // per block: {q0, qe, kb, ke}
__device__ int   g_nblk[MAXB];
__device__ float g_tq[MAXB * TQ_NCH * (HD + 2)];

// ---------------------------------------------------------------------------
// Kernel A: stable counting sort by label + cluster-aligned block table.
// ---------------------------------------------------------------------------
__global__ void sort_kernel(const int* __restrict__ lab32)
{
    __shared__ int cnt[8][256];
    __shared__ int ex[8][256];
    __shared__ int tot[8];
    __shared__ int segstart[8];
    __shared__ int sh_is64;

    const int b = blockIdx.x;
    const int tid = threadIdx.x;

    if (tid == 0) {
        int f = 1;
        #pragma unroll
        for (int k = 0; k < 32; k++)
            if (lab32[2 * k + 1] != 0) { f = 0; break; }
        sh_is64 = f;
    }
    __syncthreads();
    const int is64 = sh_is64;
    const int labbase = b * LM1;

    int mylab[16];
    int lh[8] = {0, 0, 0, 0, 0, 0, 0, 0};
    #pragma unroll
    for (int k = 0; k < 16; k++) {
        int i = tid * 16 + k;
        int l = -1;
        if (i < LM1) {
            int gi = labbase + i;
            l = lab32[is64 ? (2 * gi) : gi];
            lh[l]++;
        }
        mylab[k] = l;
    }
    #pragma unroll
    for (int l = 0; l < 8; l++) cnt[l][tid] = lh[l];
    __syncthreads();

    {
        int w = tid >> 5, lane = tid & 31;
        int carry = 0;
        for (int c = 0; c < 8; c++) {
            int t = c * 32 + lane;
            int v = cnt[w][t];
            int x = v;
            #pragma unroll
            for (int o = 1; o < 32; o <<= 1) {
                int y = __shfl_up_sync(0xffffffffu, x, o);
                if (lane >= o) x += y;
            }
            ex[w][t] = carry + x - v;
            carry += __shfl_sync(0xffffffffu, x, 31);
        }
        if (lane == 0) tot[w] = carry;
    }
    __syncthreads();

    if (tid == 0) {
        int s = 0;
        int nb = 0;
        #pragma unroll
        for (int l = 0; l < 8; l++) {
            segstart[l] = s;
            int e = s + tot[l];
            // cluster-aligned blocks: each owns <=64 queries of cluster l only
            int kb = s & ~(BN - 1);
            int ke = min((e + BN - 1) & ~(BN - 1), LSEQ);
            for (int q0 = s; q0 < e; q0 += BM) {
                g_btab[b * MAXBLK + nb] = make_int4(q0, e, kb, ke);
                nb++;
            }
            s = e;
        }
        g_nblk[b] = nb;
        g_perm[b * LSEQ + LM1] = LM1;
        g_slab[b * LSEQ + LM1] = -2;
    }
    __syncthreads();

    int run[8] = {0, 0, 0, 0, 0, 0, 0, 0};
    #pragma unroll
    for (int k = 0; k < 16; k++) {
        int l = mylab[k];
        if (l >= 0) {
            int pos = segstart[l] + ex[l][tid] + run[l]++;
            int i = tid * 16 + k;
            g_perm[b * LSEQ + pos] = i;
            g_slab[b * LSEQ + pos] = l;
        }
    }
}

// ---------------------------------------------------------------------------
// Kernel B: gather Q/K/V rows into sorted order (float4 granularity).
// ---------------------------------------------------------------------------
__global__ void gather_kernel(const float* __restrict__ Q,
                              const float* __restrict__ K,
                              const float* __restrict__ V)
{
    int idx = blockIdx.x * blockDim.x + threadIdx.x;
    int r = idx >> 4;
    int c = idx & 15;
    int b = r >> 12;
    int src = g_perm[r];
    long long so = ((long long)(b << 12) + src) * 16 + c;
    ((float4*)g_Qs)[r * 16 + c] = ((const float4*)Q)[so];
    ((float4*)g_Ks)[r * 16 + c] = ((const float4*)K)[so];
    ((float4*)g_Vs)[r * 16 + c] = ((const float4*)V)[so];
}

// ---------------------------------------------------------------------------
// Kernel C: block-sparse flash attention, cluster-aligned blocks.
// ---------------------------------------------------------------------------
__global__ __launch_bounds__(NTHREADS, 2)
void clustered_attn_kernel(float* __restrict__ Out)
{
    extern __shared__ float sm[];
    float* Qt = sm;                  // [HD][PAD]
    float* Kt = Qt + HD * PAD;       // [HD][PAD]
    float* Pt = Kt + HD * PAD;       // [BN][PAD]
    float* Vs = Pt + BN * PAD;       // [BN][HD]
    __shared__ int klabs[BN];
    __shared__ float kt[HD];
    __shared__ float vt[HD];

    const int b   = blockIdx.y;
    if (blockIdx.x >= g_nblk[b]) return;
    const int4 blk = g_btab[b * MAXBLK + blockIdx.x];
    const int q0 = blk.x, qe = blk.y, kb = blk.z, ke = blk.w;

    const int tid = threadIdx.x;
    const int tx  = tid & 15;
    const int ty  = tid >> 4;
    const float scale = 0.125f;

    const float* Qb = g_Qs + b * LSEQ * HD;
    const float* Kb = g_Ks + b * LSEQ * HD;
    const float* Vb = g_Vs + b * LSEQ * HD;
    const int* slab = g_slab + b * LSEQ;

    // ---- load Q tile (rows clamped; out-of-segment rows are masked + unwritten)
    #pragma unroll
    for (int idx = tid; idx < BM * HD; idx += NTHREADS) {
        int m = idx >> 6, d = idx & 63;
        int rr = min(q0 + m, LM1);
        Qt[d * PAD + m] = Qb[rr * HD + d];
    }
    if (tid < HD) kt[tid] = Kb[LM1 * HD + tid];
    else if (tid < 2 * HD) vt[tid - HD] = Vb[LM1 * HD + (tid - HD)];

    int qlab[4];
    #pragma unroll
    for (int i = 0; i < 4; i++) {
        int r = q0 + ty * 4 + i;
        qlab[i] = (r < qe) ? slab[r] : -3;   // -3 matches nothing
    }

    float mrow[4], lrow[4], acc[4][4];
    #pragma unroll
    for (int i = 0; i < 4; i++) {
        mrow[i] = -INFINITY;
        lrow[i] = 0.0f;
        #pragma unroll
        for (int j = 0; j < 4; j++) acc[i][j] = 0.0f;
    }

    for (int n0 = kb; n0 < ke; n0 += BN) {
        __syncthreads();

        #pragma unroll
        for (int idx = tid; idx < BN * HD; idx += NTHREADS) {
            int n = idx >> 6, d = idx & 63;
            Kt[d * PAD + n] = Kb[(n0 + n) * HD + d];
            Vs[n * HD + d]  = Vb[(n0 + n) * HD + d];
        }
        if (tid < BN) klabs[tid] = slab[n0 + tid];
        __syncthreads();

        float s[4][4];
        #pragma unroll
        for (int i = 0; i < 4; i++)
            #pragma unroll
            for (int j = 0; j < 4; j++) s[i][j] = 0.0f;

        #pragma unroll 8
        for (int d = 0; d < HD; d++) {
            float a[4], bb[4];
            #pragma unroll
            for (int i = 0; i < 4; i++) a[i]  = Qt[d * PAD + 4 * ty + i];
            #pragma unroll
            for (int j = 0; j < 4; j++) bb[j] = Kt[d * PAD + 4 * tx + j];
            #pragma unroll
            for (int i = 0; i < 4; i++)
                #pragma unroll
                for (int j = 0; j < 4; j++) s[i][j] += a[i] * bb[j];
        }

        int klj[4];
        #pragma unroll
        for (int j = 0; j < 4; j++) klj[j] = klabs[4 * tx + j];

        #pragma unroll
        for (int i = 0; i < 4; i++)
            #pragma unroll
            for (int j = 0; j < 4; j++)
                s[i][j] = (qlab[i] == klj[j]) ? s[i][j] * scale : -INFINITY;

        #pragma unroll
        for (int i = 0; i < 4; i++) {
            float tm = fmaxf(fmaxf(s[i][0], s[i][1]), fmaxf(s[i][2], s[i][3]));
            #pragma unroll
            for (int o = 8; o >= 1; o >>= 1)
                tm = fmaxf(tm, __shfl_xor_sync(0xffffffffu, tm, o));

            float newm = fmaxf(mrow[i], tm);
            float mref = (newm == -INFINITY) ? 0.0f : newm;
            float f = __expf(mrow[i] - mref);

            float rs = 0.0f;
            #pragma unroll
            for (int j = 0; j < 4; j++) {
                float p = __expf(s[i][j] - mref);
                s[i][j] = p;
                rs += p;
            }
            #pragma unroll
            for (int o = 8; o >= 1; o >>= 1)
                rs += __shfl_xor_sync(0xffffffffu, rs, o);

            lrow[i] = lrow[i] * f + rs;
            mrow[i] = newm;
            #pragma unroll
            for (int j = 0; j < 4; j++) acc[i][j] *= f;
        }

        #pragma unroll
        for (int i = 0; i < 4; i++)
            #pragma unroll
            for (int j = 0; j < 4; j++)
                Pt[(4 * tx + j) * PAD + (4 * ty + i)] = s[i][j];
        __syncthreads();

        #pragma unroll 8
        for (int n = 0; n < BN; n++) {
            float a[4], bb[4];
            #pragma unroll
            for (int i = 0; i < 4; i++) a[i]  = Pt[n * PAD + 4 * ty + i];
            #pragma unroll
            for (int j = 0; j < 4; j++) bb[j] = Vs[n * HD + 4 * tx + j];
            #pragma unroll
            for (int i = 0; i < 4; i++)
                #pragma unroll
                for (int j = 0; j < 4; j++) acc[i][j] += a[i] * bb[j];
        }
    }

    // ---- time key column (every real query attends to it)
    #pragma unroll
    for (int i = 0; i < 4; i++) {
        float part = 0.0f;
        #pragma unroll
        for (int jj = 0; jj < 4; jj++)
            part += Qt[(4 * tx + jj) * PAD + (4 * ty + i)] * kt[4 * tx + jj];
        #pragma unroll
        for (int o = 8; o >= 1; o >>= 1)
            part += __shfl_xor_sync(0xffffffffu, part, o);
        float st = part * scale;

        float newm = fmaxf(mrow[i], st);
        float f = __expf(mrow[i] - newm);
        float p = __expf(st - newm);
        lrow[i] = lrow[i] * f + p;
        mrow[i] = newm;
        #pragma unroll
        for (int j = 0; j < 4; j++)
            acc[i][j] = acc[i][j] * f + p * vt[4 * tx + j];
    }

    // ---- epilogue: normalize + scatter (only rows owned by this block)
    #pragma unroll
    for (int i = 0; i < 4; i++) {
        int r = q0 + 4 * ty + i;
        if (r < qe) {
            float inv = 1.0f / lrow[i];
            int orig = g_perm[b * LSEQ + r];
            float4 o4;
            o4.x = acc[i][0] * inv;
            o4.y = acc[i][1] * inv;
            o4.z = acc[i][2] * inv;
            o4.w = acc[i][3] * inv;
            *reinterpret_cast<float4*>(&Out[((long long)b * LSEQ + orig) * HD + 4 * tx]) = o4;
        }
    }
}

// ---------------------------------------------------------------------------
// Kernel D1: time-query partials.
// ---------------------------------------------------------------------------
__global__ void timeq_part(const float* __restrict__ Q,
                           const float* __restrict__ K,
                           const float* __restrict__ V)
{
    __shared__ float q[HD];
    __shared__ float p[TQ_CHUNKS];
    __shared__ float red[128];
    __shared__ float vacc[2][HD];

    const int b = blockIdx.x >> 5;
    const int c = blockIdx.x & 31;
    const int tid = threadIdx.x;
    const float scale = 0.125f;
    const long long base = (long long)b * LSEQ;

    if (tid < HD) q[tid] = Q[(base + LM1) * HD + tid];
    __syncthreads();

    const int j = c * TQ_CHUNKS + tid;
    const float* kr = K + (base + j) * HD;
    float dot = 0.0f;
    #pragma unroll
    for (int d = 0; d < HD; d += 4) {
        float4 k4 = *reinterpret_cast<const float4*>(kr + d);
        dot += q[d] * k4.x + q[d + 1] * k4.y + q[d + 2] * k4.z + q[d + 3] * k4.w;
    }
    dot *= scale;

    float m = dot;
    #pragma unroll
    for (int o = 16; o >= 1; o >>= 1)
        m = fmaxf(m, __shfl_xor_sync(0xffffffffu, m, o));
    if ((tid & 31) == 0) red[tid >> 5] = m;
    __syncthreads();
    m = fmaxf(fmaxf(red[0], red[1]), fmaxf(red[2], red[3]));

    float pv = __expf(dot - m);
    p[tid] = pv;

    float s = pv;
    #pragma unroll
    for (int o = 16; o >= 1; o >>= 1)
        s += __shfl_xor_sync(0xffffffffu, s, o);
    if ((tid & 31) == 0) red[4 + (tid >> 5)] = s;
    __syncthreads();
    s = red[4] + red[5] + red[6] + red[7];

    const int d = tid & 63, h = tid >> 6;
    float a = 0.0f;
    #pragma unroll 8
    for (int jj = h * 64; jj < h * 64 + 64; jj++)
        a += p[jj] * V[(base + c * TQ_CHUNKS + jj) * HD + d];
    vacc[h][d] = a;
    __syncthreads();

    float* out = g_tq + (b * TQ_NCH + c) * (HD + 2);
    if (tid < HD) out[tid] = vacc[0][tid] + vacc[1][tid];
    else if (tid == HD) { out[HD] = m; out[HD + 1] = s; }
}

// ---------------------------------------------------------------------------
// Kernel D2: combine time-query partials.
// ---------------------------------------------------------------------------
__global__ void timeq_combine(float* __restrict__ Out)
{
    const int b = blockIdx.x;
    const int tid = threadIdx.x;
    const float* part = g_tq + b * TQ_NCH * (HD + 2);

    float M = -INFINITY;
    #pragma unroll
    for (int c = 0; c < TQ_NCH; c++)
        M = fmaxf(M, part[c * (HD + 2) + HD]);

    float stot = 0.0f, a = 0.0f;
    #pragma unroll
    for (int c = 0; c < TQ_NCH; c++) {
        float f = __expf(part[c * (HD + 2) + HD] - M);
        stot += part[c * (HD + 2) + HD + 1] * f;
        a    += part[c * (HD + 2) + tid] * f;
    }
    Out[((long long)b * LSEQ + LM1) * HD + tid] = a / stot;
}

// ---------------------------------------------------------------------------
extern "C" void kernel_launch(void* const* d_in, const int* in_sizes, int n_in,
                              void* d_out, int out_size)
{
    const float* Q = (const float*)d_in[0];
    const float* K = (const float*)d_in[1];
    const float* V = (const float*)d_in[2];
    const int* lab = (const int*)d_in[3];
    float* Out = (float*)d_out;

    const int B = in_sizes[0] / (LSEQ * HD);

    sort_kernel<<<B, 256>>>(lab);
    gather_kernel<<<B * 256, 256>>>(Q, K, V);

    const int smem_bytes = (HD * PAD + HD * PAD + BN * PAD + BN * HD) * (int)sizeof(float);
    cudaFuncSetAttribute(clustered_attn_kernel,
                         cudaFuncAttributeMaxDynamicSharedMemorySize, smem_bytes);
    dim3 grid(MAXBLK, B);
    clustered_attn_kernel<<<grid, NTHREADS, smem_bytes>>>(Out);

    timeq_part<<<B * TQ_NCH, 128>>>(Q, K, V);
    timeq_combine<<<B, HD>>>(Out);
}